// round 7
// baseline (speedup 1.0000x reference)
#include <cuda_runtime.h>
#include <cuda_bf16.h>

// Canny edge detection, exact replica of the JAX reference.
// Strip view: (B*H, W) = (8192, 512). Bitmask: 8 u64 (16 u32) words per row.

#define HH 8192
#define WD 512
#define TROWS 320          // hysteresis tile rows: 64 interior + 2*128 halo
#define HALO 128
#define INT_ROWS 64
#define HPITCH 9           // padded u64 pitch in shared

__device__ unsigned long long g_strong[HH * 8];
__device__ unsigned long long g_weak[HH * 8];
__device__ unsigned long long g_tmp[HH * 8];

__device__ __forceinline__ float quant(float v) {
    float t = floorf(((v + 1.0f) * 0.5f) * 255.0f);
    return fminf(fmaxf(t, 0.0f), 255.0f);
}

// ---------------------------------------------------------------------------
// Kernel 1: quantize -> Sobel (replicate pad) -> channel argmax -> NMS (zero
// pad) -> thresholds -> strong/weak bitmasks.  Register-rolling warp strips:
// each warp = 32 columns x 32 output rows, no shared memory, neighbors via
// shuffles; lanes 0/31 compute one redundant halo column each.
// ---------------------------------------------------------------------------
__global__ __launch_bounds__(256) void k_grad(const float* __restrict__ xin) {
    const unsigned FULL = 0xffffffffu;
    const int wib  = threadIdx.x >> 5;
    const int lane = threadIdx.x & 31;
    const int wg   = blockIdx.x * 8 + wib;        // 0..4095
    const int wx   = wg & 15;                     // x-warp 0..15
    const int y0   = (wg >> 4) * 32;              // strip start row
    const int x0   = wx * 32;
    const int x    = x0 + lane;
    const bool isL = (lane == 0), isR = (lane == 31);
    const bool isE = isL || isR;
    const bool hasL = (wx > 0), hasR = (wx < 15);
    // extra (halo) column coords for lane0 / lane31 (img replicate clamp)
    const int ex1 = isL ? max(x0 - 1, 0) : min(x0 + 32, WD - 1);
    const int ex2 = isL ? max(x0 - 2, 0) : min(x0 + 33, WD - 1);

    // rolling Sobel state (rows g-1, g-2) per channel
    float a1[3] = {0, 0, 0}, a2[3] = {0, 0, 0};
    float d1[3] = {0, 0, 0}, d2[3] = {0, 0, 0};
    float ae1[3] = {0, 0, 0}, ae2[3] = {0, 0, 0};
    float de1[3] = {0, 0, 0}, de2[3] = {0, 0, 0};
    // rolling mag / neighbor-mag / grad windows (rows t-1, t, t+1)
    float mP = 0, mC = 0, mN = 0;
    float lmP = 0, lmC = 0, lmN = 0;
    float rmP = 0, rmC = 0, rmN = 0;
    float gxC = 0, gyC = 0, gxN = 0, gyN = 0;

    auto gaddr = [&](int gy, int ch, int xx) -> long {
        int gc = min(max(gy, 0), HH - 1);          // replicate clamp (strip)
        int b = gc >> 9, y = gc & 511;
        return (long)((((b * 3 + ch) << 9) + y) * 512 + xx);
    };

    float cur[3], curE1[3] = {0, 0, 0}, curE2[3] = {0, 0, 0};
#pragma unroll
    for (int ch = 0; ch < 3; ++ch) {
        cur[ch] = xin[gaddr(y0 - 2, ch, x)];
        if (isE) {
            curE1[ch] = xin[gaddr(y0 - 2, ch, ex1)];
            curE2[ch] = xin[gaddr(y0 - 2, ch, ex2)];
        }
    }

    for (int yy = 0; yy < 36; ++yy) {
        // prefetch next img row
        float nxtv[3] = {0, 0, 0}, nE1[3] = {0, 0, 0}, nE2[3] = {0, 0, 0};
        if (yy < 35) {
            int g = y0 - 1 + yy;
#pragma unroll
            for (int ch = 0; ch < 3; ++ch) {
                nxtv[ch] = xin[gaddr(g, ch, x)];
                if (isE) {
                    nE1[ch] = xin[gaddr(g, ch, ex1)];
                    nE2[ch] = xin[gaddr(g, ch, ex2)];
                }
            }
        }

        // horizontal Sobel partials at img row g = y0-2+yy
        float a0[3], d0[3], ae0[3], de0[3];
#pragma unroll
        for (int ch = 0; ch < 3; ++ch) {
            float v  = quant(cur[ch]);
            float lf = __shfl_up_sync(FULL, v, 1);
            float rt = __shfl_down_sync(FULL, v, 1);
            float e1 = quant(curE1[ch]);
            float e2 = quant(curE2[ch]);
            if (isL) lf = e1;                      // replicate-clamped halo
            if (isR) rt = e1;
            a0[ch] = lf + 2.0f * v + rt;
            d0[ch] = rt - lf;
            // extra column: lane0 col x0-1 (neighbors e2, v); lane31 col
            // x0+32 (neighbors v, e2)
            float el = isL ? e2 : v;
            float er = isL ? v : e2;
            ae0[ch] = el + 2.0f * e1 + er;
            de0[ch] = er - el;
        }

        // mag at row m = g-1 (valid yy >= 2)
        if (yy >= 2) {
            float bm = -1.0f, bgx = 0.0f, bgy = 0.0f, bmE = -1.0f;
#pragma unroll
            for (int ch = 0; ch < 3; ++ch) {
                float gx = d2[ch] + 2.0f * d1[ch] + d0[ch];
                float gy = a0[ch] - a2[ch];
                float mg = fabsf(gx) + fabsf(gy);
                if (mg > bm) { bm = mg; bgx = gx; bgy = gy; }
                float gxE = de2[ch] + 2.0f * de1[ch] + de0[ch];
                float gyE = ae0[ch] - ae2[ch];
                float mgE = fabsf(gxE) + fabsf(gyE);
                if (mgE > bmE) bmE = mgE;
            }
            float lm_new = __shfl_up_sync(FULL, bm, 1);
            float rm_new = __shfl_down_sync(FULL, bm, 1);
            if (isL) lm_new = hasL ? bmE : 0.0f;   // zero-pad NMS at x edges
            if (isR) rm_new = hasR ? bmE : 0.0f;
            mP = mC; mC = mN; mN = bm;
            lmP = lmC; lmC = lmN; lmN = lm_new;
            rmP = rmC; rmC = rmN; rmN = rm_new;
            gxC = gxN; gyC = gyN; gxN = bgx; gyN = bgy;
        }

        // NMS + thresholds at row t = y0-4+yy (valid yy >= 4)
        if (yy >= 4) {
            int t = y0 - 4 + yy;
            float up_m = mP, up_l = lmP, up_r = rmP;
            float dn_m = mN, dn_l = lmN, dn_r = rmN;
            if (t == 0)      { up_m = 0; up_l = 0; up_r = 0; }  // zero-pad y
            if (t == HH - 1) { dn_m = 0; dn_l = 0; dn_r = 0; }
            float mg = mC, gx = gxC, gy = gyC;
            float ax = fabsf(gx), ay = fabsf(gy);
            const float TG22 = 0.4142135623730951f;
            bool is_h = ay < TG22 * ax;
            bool is_v = ay * TG22 > ax;
            bool same = (gx * gy) >= 0.0f;
            float n1 = is_h ? lmC : (is_v ? up_m : (same ? up_l : up_r));
            float n2 = is_h ? rmC : (is_v ? dn_m : (same ? dn_r : dn_l));
            bool keep   = (mg > n1) && (mg >= n2);
            bool strong = keep && (mg > 200.0f);
            bool weak   = keep && (mg > 100.0f);
            unsigned bs = __ballot_sync(FULL, strong);
            unsigned bw = __ballot_sync(FULL, weak);
            if (isL) {
                ((unsigned*)g_strong)[t * 16 + wx] = bs;
                ((unsigned*)g_weak)[t * 16 + wx]   = bw;
            }
        }

        // roll
#pragma unroll
        for (int ch = 0; ch < 3; ++ch) {
            a2[ch] = a1[ch]; a1[ch] = a0[ch];
            d2[ch] = d1[ch]; d1[ch] = d0[ch];
            ae2[ch] = ae1[ch]; ae1[ch] = ae0[ch];
            de2[ch] = de1[ch]; de1[ch] = de0[ch];
            cur[ch] = nxtv[ch]; curE1[ch] = nE1[ch]; curE2[ch] = nE2[ch];
        }
    }
}

// ---------------------------------------------------------------------------
// Kernel 2: hysteresis — exactly (up to) 128 Jacobi dilation steps per launch
// (4 launches = the reference's 512-step cap, bit-exact). 128 blocks, each:
// 64 interior rows + 128-row halo each side, double-buffered shared, early
// break on tile convergence. Final launch expands straight to float output.
// ---------------------------------------------------------------------------
__global__ __launch_bounds__(256) void k_hyst(int dir, float* __restrict__ out,
                                              int final_pass) {
    __shared__ unsigned long long bufA[TROWS * HPITCH];
    __shared__ unsigned long long bufB[TROWS * HPITCH];

    const unsigned long long* __restrict__ src = dir ? g_tmp : g_strong;
    unsigned long long* __restrict__ dst = dir ? g_strong : g_tmp;

    const int tid = threadIdx.x;
    const int base = blockIdx.x * INT_ROWS;

    for (int i = tid; i < TROWS * 8; i += 256) {
        int r = i >> 3, cc = i & 7;
        int gr = base - HALO + r;
        bufA[r * HPITCH + cc] = (gr >= 0 && gr < HH) ? src[gr * 8 + cc] : 0ull;
    }

    const int c = tid & 7;
    const int r0 = (tid >> 3) * 10;
    unsigned long long swr[10];
#pragma unroll
    for (int k = 0; k < 10; ++k) {
        int gr = base - HALO + r0 + k;
        swr[k] = (gr >= 0 && gr < HH) ? g_weak[gr * 8 + c] : 0ull;
    }
    __syncthreads();

    unsigned long long* cur = bufA;
    unsigned long long* nxt = bufB;

    for (int it = 0; it < 128; ++it) {
        auto hload = [&](int r, unsigned long long& h, unsigned long long& w) {
            if ((unsigned)r >= (unsigned)TROWS) { h = 0ull; w = 0ull; return; }
            unsigned long long ww = cur[r * HPITCH + c];
            unsigned long long wl = (c > 0) ? cur[r * HPITCH + c - 1] : 0ull;
            unsigned long long wr = (c < 7) ? cur[r * HPITCH + c + 1] : 0ull;
            w = ww;
            h = ww | (ww << 1) | (ww >> 1) | (wl >> 63) | (wr << 63);
        };
        unsigned long long Hm, H0, Hp, w0, wp, wd;
        hload(r0 - 1, Hm, wd);
        hload(r0, H0, w0);
        bool changed = false;
#pragma unroll
        for (int k = 0; k < 10; ++k) {
            hload(r0 + k + 1, Hp, wp);
            unsigned long long nw = ((Hm | H0 | Hp) & swr[k]) | w0;
            nxt[(r0 + k) * HPITCH + c] = nw;
            changed |= (nw != w0);
            Hm = H0; H0 = Hp; w0 = wp;
        }
        int any = __syncthreads_or(changed ? 1 : 0);
        unsigned long long* t = cur; cur = nxt; nxt = t;
        if (!any) break;
    }

    if (!final_pass) {
        for (int i = tid; i < INT_ROWS * 8; i += 256) {
            int rr = i >> 3, cc = i & 7;
            dst[(base + rr) * 8 + cc] = cur[(HALO + rr) * HPITCH + cc];
        }
    } else {
        // expand interior rows to (B,3,H,W) floats in {-1,+1}
        for (int i = tid; i < INT_ROWS * 128; i += 256) {
            int rr = i >> 7, qx = i & 127;
            int t = base + rr, X = qx << 2;
            unsigned long long w = cur[(HALO + rr) * HPITCH + (X >> 6)];
            int sh = X & 63;
            float4 v;
            v.x = ((w >> sh) & 1ull) ? 1.0f : -1.0f;
            v.y = ((w >> (sh + 1)) & 1ull) ? 1.0f : -1.0f;
            v.z = ((w >> (sh + 2)) & 1ull) ? 1.0f : -1.0f;
            v.w = ((w >> (sh + 3)) & 1ull) ? 1.0f : -1.0f;
            int b = t >> 9, y = t & 511;
#pragma unroll
            for (int ch = 0; ch < 3; ++ch)
                *(float4*)&out[(((b * 3 + ch) << 9) + y) * 512 + X] = v;
        }
    }
}

extern "C" void kernel_launch(void* const* d_in, const int* in_sizes, int n_in,
                              void* d_out, int out_size) {
    const float* x = (const float*)d_in[0];
    float* out = (float*)d_out;

    k_grad<<<512, 256>>>(x);                 // 4096 warps: 16 x-warps x 256 strips
    k_hyst<<<128, 256>>>(0, nullptr, 0);     // steps   1..128  strong -> tmp
    k_hyst<<<128, 256>>>(1, nullptr, 0);     // steps 129..256  tmp -> strong
    k_hyst<<<128, 256>>>(0, nullptr, 0);     // steps 257..384  strong -> tmp
    k_hyst<<<128, 256>>>(1, out, 1);         // steps 385..512  tmp -> float out
}

// round 11
// speedup vs baseline: 1.0195x; 1.0195x over previous
#include <cuda_runtime.h>
#include <cuda_bf16.h>

// Canny edge detection, exact replica of the JAX reference.
// Strip view: (B*H, W) = (8192, 512). Bitmask: 8 u64 (16 u32) words per row.

#define HH 8192
#define WD 512
#define TROWS 320          // hysteresis tile rows: 64 interior + 2*128 halo
#define HALO 128
#define INT_ROWS 64
#define HPITCH 9           // padded u64 pitch in shared

__device__ unsigned long long g_strong[HH * 8];
__device__ unsigned long long g_weak[HH * 8];
__device__ unsigned long long g_tmp[HH * 8];

__device__ __forceinline__ float quant(float v) {
    float t = floorf(((v + 1.0f) * 0.5f) * 255.0f);
    return fminf(fmaxf(t, 0.0f), 255.0f);
}

// ---------------------------------------------------------------------------
// Kernel 1: quantize -> Sobel (replicate pad on strip) -> channel argmax ->
//   NMS (zero pad) -> thresholds -> strong/weak bitmasks.
// 64x64 output tile per block, 256 threads.
//   Phase 1: load+quantize 68x68x3 img tile to smem.
//   Phase 2: column-rolling Sobel: 1 thread per (mag column, row segment),
//            3 smem reads per pixel per channel (vs 8 naive).
//   Phase 3: column-rolling NMS: 1 thread per (output column, 16-row seg),
//            warp lanes = 32 adjacent columns -> ballot packs bits.
// ---------------------------------------------------------------------------
#define IMP 68              // img tile pitch / height (coords -2..65)
#define MAGP 68             // mag tile pitch (66 used)
#define GXP 65              // gx/gy pitch (64 used)

__global__ __launch_bounds__(256) void k_grad(const float* __restrict__ xin) {
    extern __shared__ float sm[];
    float* simg = sm;                          // 3 * 68 * 68
    float* smag = simg + 3 * IMP * IMP;        // 66 * 68
    float* sgx  = smag + 66 * MAGP;            // 64 * 65
    float* sgy  = sgx + 64 * GXP;              // 64 * 65

    const int tid = threadIdx.x;
    const int x0 = blockIdx.x * 64;
    const int Y0 = blockIdx.y * 64;

    // Phase 1: quantized img tile, replicate clamp at strip edges.
    for (int i = tid; i < IMP * IMP; i += 256) {
        int yy = i / IMP, xx = i - yy * IMP;
        int GY = Y0 - 2 + yy; GY = max(0, min(HH - 1, GY));
        int GX = x0 - 2 + xx; GX = max(0, min(WD - 1, GX));
        int b = GY >> 9, y = GY & 511;
        const float* base = xin + (long)(((b * 3) << 9) + y) * 512 + GX;
#pragma unroll
        for (int ch = 0; ch < 3; ++ch)
            simg[ch * IMP * IMP + i] = quant(base[(long)ch << 18]);
    }
    __syncthreads();

    // Phase 2: mag region 66 rows x 66 cols (coords -1..64 both dims).
    // mag idx m <-> img rows m, m+1, m+2 ; mag col cc <-> img cols cc..cc+2.
    for (int item = tid; item < 264; item += 256) {
        int seg = item / 66;
        int cc  = item - seg * 66;
        int m0 = seg * 17;
        int m1 = min(66, m0 + 17);
        float A0[3], A1[3], A2[3], D0[3], D1[3], D2[3];
#pragma unroll
        for (int ch = 0; ch < 3; ++ch) {
            const float* ip = simg + ch * IMP * IMP + cc;
            float v0 = ip[m0 * IMP], v1 = ip[m0 * IMP + 1], v2 = ip[m0 * IMP + 2];
            A0[ch] = v0 + 2.0f * v1 + v2; D0[ch] = v2 - v0;
            v0 = ip[(m0 + 1) * IMP]; v1 = ip[(m0 + 1) * IMP + 1]; v2 = ip[(m0 + 1) * IMP + 2];
            A1[ch] = v0 + 2.0f * v1 + v2; D1[ch] = v2 - v0;
        }
        for (int m = m0; m < m1; ++m) {
            float bm = -1.0f, bgx = 0.0f, bgy = 0.0f;
#pragma unroll
            for (int ch = 0; ch < 3; ++ch) {
                const float* ip = simg + ch * IMP * IMP + cc + (m + 2) * IMP;
                float v0 = ip[0], v1 = ip[1], v2 = ip[2];
                A2[ch] = v0 + 2.0f * v1 + v2; D2[ch] = v2 - v0;
                float gx = D0[ch] + 2.0f * D1[ch] + D2[ch];
                float gy = A2[ch] - A0[ch];
                float mg = fabsf(gx) + fabsf(gy);
                if (mg > bm) { bm = mg; bgx = gx; bgy = gy; }
                A0[ch] = A1[ch]; A1[ch] = A2[ch];
                D0[ch] = D1[ch]; D1[ch] = D2[ch];
            }
            smag[m * MAGP + cc] = bm;
            if (m >= 1 && m <= 64 && cc >= 1 && cc <= 64) {
                sgx[(m - 1) * GXP + (cc - 1)] = bgx;
                sgy[(m - 1) * GXP + (cc - 1)] = bgy;
            }
        }
    }
    __syncthreads();

    // Phase 3: NMS + thresholds, column rolling. 8 warps:
    //   warp w: col group g = w&1 (cols g*32..+31), seg = w>>1 (rows seg*16..+15)
    const unsigned FULL = 0xffffffffu;
    const int wid = tid >> 5, lane = tid & 31;
    const int g = wid & 1, seg3 = wid >> 1;
    const int c = g * 32 + lane;               // interior col 0..63
    const int X = x0 + c;
    const int mr0 = seg3 * 16;                 // top mag row of first window
    const float TG22 = 0.4142135623730951f;

    float w00 = smag[mr0 * MAGP + c], w01 = smag[mr0 * MAGP + c + 1], w02 = smag[mr0 * MAGP + c + 2];
    float w10 = smag[(mr0 + 1) * MAGP + c], w11 = smag[(mr0 + 1) * MAGP + c + 1], w12 = smag[(mr0 + 1) * MAGP + c + 2];

#pragma unroll 4
    for (int k = 0; k < 16; ++k) {
        int mrow = mr0 + k + 2;
        float w20 = smag[mrow * MAGP + c];
        float w21 = smag[mrow * MAGP + c + 1];
        float w22 = smag[mrow * MAGP + c + 2];
        int row = seg3 * 16 + k;
        int t = Y0 + row;
        float gx = sgx[row * GXP + c];
        float gy = sgy[row * GXP + c];

        // zero-pad NMS neighbors at GLOBAL image edges
        float a00 = w00, a01 = w01, a02 = w02;
        float a10 = w10, a12 = w12;
        float a20 = w20, a21 = w21, a22 = w22;
        if (X == 0)      { a00 = 0; a10 = 0; a20 = 0; }
        if (X == WD - 1) { a02 = 0; a12 = 0; a22 = 0; }
        if (t == 0)      { a00 = 0; a01 = 0; a02 = 0; }
        if (t == HH - 1) { a20 = 0; a21 = 0; a22 = 0; }

        float ax = fabsf(gx), ay = fabsf(gy);
        bool is_h = ay < TG22 * ax;
        bool is_v = ay * TG22 > ax;
        bool same = (gx * gy) >= 0.0f;
        float n1 = is_h ? a10 : (is_v ? a01 : (same ? a00 : a02));
        float n2 = is_h ? a12 : (is_v ? a21 : (same ? a22 : a20));
        float mg = w11;
        bool keep   = (mg > n1) && (mg >= n2);
        bool strong = keep && (mg > 200.0f);
        bool weak   = keep && (mg > 100.0f);
        unsigned bs = __ballot_sync(FULL, strong);
        unsigned bw = __ballot_sync(FULL, weak);
        if (lane == 0) {
            int u32idx = t * 16 + (x0 >> 5) + g;
            ((unsigned*)g_strong)[u32idx] = bs;
            ((unsigned*)g_weak)[u32idx]   = bw;
        }
        w00 = w10; w01 = w11; w02 = w12;
        w10 = w20; w11 = w21; w12 = w22;
    }
}

// ---------------------------------------------------------------------------
// Kernel 2: hysteresis — exactly (up to) 128 Jacobi dilation steps per launch
// (4 launches = the reference's 512-step cap, bit-exact). 128 blocks x 512
// threads (5 rows/thread — short dependency chain), 64 interior rows +
// 128-row halo each side, double-buffered shared, early break on convergence.
// ---------------------------------------------------------------------------
__global__ __launch_bounds__(512) void k_hyst(int dir) {
    __shared__ unsigned long long bufA[TROWS * HPITCH];
    __shared__ unsigned long long bufB[TROWS * HPITCH];

    const unsigned long long* __restrict__ src = dir ? g_tmp : g_strong;
    unsigned long long* __restrict__ dst = dir ? g_strong : g_tmp;

    const int tid = threadIdx.x;
    const int base = blockIdx.x * INT_ROWS;

    for (int i = tid; i < TROWS * 8; i += 512) {
        int r = i >> 3, cc = i & 7;
        int gr = base - HALO + r;
        bufA[r * HPITCH + cc] = (gr >= 0 && gr < HH) ? src[gr * 8 + cc] : 0ull;
    }

    const int c = tid & 7;
    const int r0 = (tid >> 3) * 5;
    unsigned long long swr[5];
#pragma unroll
    for (int k = 0; k < 5; ++k) {
        int gr = base - HALO + r0 + k;
        swr[k] = (gr >= 0 && gr < HH) ? g_weak[gr * 8 + c] : 0ull;
    }
    __syncthreads();

    unsigned long long* cur = bufA;
    unsigned long long* nxt = bufB;

    for (int it = 0; it < 128; ++it) {
        auto hload = [&](int r, unsigned long long& h, unsigned long long& w) {
            if ((unsigned)r >= (unsigned)TROWS) { h = 0ull; w = 0ull; return; }
            unsigned long long ww = cur[r * HPITCH + c];
            unsigned long long wl = (c > 0) ? cur[r * HPITCH + c - 1] : 0ull;
            unsigned long long wr = (c < 7) ? cur[r * HPITCH + c + 1] : 0ull;
            w = ww;
            h = ww | (ww << 1) | (ww >> 1) | (wl >> 63) | (wr << 63);
        };
        unsigned long long Hm, H0, Hp, w0, wp, wd;
        hload(r0 - 1, Hm, wd);
        hload(r0, H0, w0);
        bool changed = false;
#pragma unroll
        for (int k = 0; k < 5; ++k) {
            hload(r0 + k + 1, Hp, wp);
            unsigned long long nw = ((Hm | H0 | Hp) & swr[k]) | w0;
            nxt[(r0 + k) * HPITCH + c] = nw;
            changed |= (nw != w0);
            Hm = H0; H0 = Hp; w0 = wp;
        }
        int any = __syncthreads_or(changed ? 1 : 0);
        unsigned long long* t = cur; cur = nxt; nxt = t;
        if (!any) break;
    }

    for (int i = tid; i < INT_ROWS * 8; i += 512) {
        int rr = i >> 3, cc = i & 7;
        dst[(base + rr) * 8 + cc] = cur[(HALO + rr) * HPITCH + cc];
    }
}

// ---------------------------------------------------------------------------
// Kernel 3: bitmask -> (B,3,H,W) float output, values {-1, +1}.
// Each thread handles 2 independent pixel-quads (ILP), coalescing preserved.
// ---------------------------------------------------------------------------
__global__ __launch_bounds__(256) void k_out(float* __restrict__ out) {
    int idx = blockIdx.x * 256 + threadIdx.x;          // 0 .. 524287
#pragma unroll
    for (int half = 0; half < 2; ++half) {
        int q = idx + half * 524288;
        int p0 = q << 2;
        int Y = p0 >> 9;
        int X = p0 & 511;
        unsigned long long w = g_strong[Y * 8 + (X >> 6)];
        int sh = X & 63;
        float4 v;
        v.x = ((w >> sh) & 1ull) ? 1.0f : -1.0f;
        v.y = ((w >> (sh + 1)) & 1ull) ? 1.0f : -1.0f;
        v.z = ((w >> (sh + 2)) & 1ull) ? 1.0f : -1.0f;
        v.w = ((w >> (sh + 3)) & 1ull) ? 1.0f : -1.0f;
        int b = Y >> 9, y = Y & 511;
#pragma unroll
        for (int ch = 0; ch < 3; ++ch)
            *(float4*)&out[(((b * 3 + ch) << 9) + y) * 512 + X] = v;
    }
}

extern "C" void kernel_launch(void* const* d_in, const int* in_sizes, int n_in,
                              void* d_out, int out_size) {
    const float* x = (const float*)d_in[0];
    float* out = (float*)d_out;

    const int grad_smem = (3 * IMP * IMP + 66 * MAGP + 2 * 64 * GXP) * 4;  // 106,720 B
    cudaFuncSetAttribute(k_grad, cudaFuncAttributeMaxDynamicSharedMemorySize,
                         grad_smem);

    dim3 g1(WD / 64, HH / 64);                  // (8, 128)
    k_grad<<<g1, 256, grad_smem>>>(x);
    k_hyst<<<128, 512>>>(0);                    // steps   1..128  strong -> tmp
    k_hyst<<<128, 512>>>(1);                    // steps 129..256  tmp -> strong
    k_hyst<<<128, 512>>>(0);                    // steps 257..384  strong -> tmp
    k_hyst<<<128, 512>>>(1);                    // steps 385..512  tmp -> strong
    k_out<<<2048, 256>>>(out);
}

// round 13
// speedup vs baseline: 1.5045x; 1.4758x over previous
#include <cuda_runtime.h>
#include <cuda_bf16.h>

// Canny edge detection, exact replica of the JAX reference.
// Strip view: (B*H, W) = (8192, 512). Bitmask: 8 u64 (16 u32) words per row.

#define HH 8192
#define WD 512
#define TROWS 320          // hysteresis tile rows: 64 interior + 2*128 halo
#define HALO 128
#define INT_ROWS 64
#define HPITCH 9           // padded u64 pitch in shared

__device__ unsigned long long g_strong[HH * 8];
__device__ unsigned long long g_weak[HH * 8];
__device__ unsigned long long g_tmp[HH * 8];

__device__ __forceinline__ float quant(float v) {
    // input in [-1,1) -> result already in [0,255]; clip is redundant
    return floorf(((v + 1.0f) * 0.5f) * 255.0f);
}

// ---------------------------------------------------------------------------
// Kernel 1: quantize -> Sobel (replicate pad on strip) -> channel argmax ->
//   NMS direction code -> thresholds -> strong/weak bitmasks.
// 16x64 output tile, 256 threads, grid (8,512). smem 21 KB -> 8 blocks/SM.
//   P1: quantized 20x68x3 f32 img tile.
//   P2: 18x66 mag region, 2 px/item via float2 loads; packs mag|code<<16,
//       zero-stores words outside the global image (NMS zero-pad).
//   P3: center + 2 code-directed neighbor reads, ballot packs bits.
// All arithmetic integer-exact in f32 -> bit-identical to the reference.
// ---------------------------------------------------------------------------
__global__ __launch_bounds__(256) void k_grad(const float* __restrict__ xin) {
    __shared__ __align__(16) float simg[3][20][68];
    __shared__ __align__(16) unsigned smag[18][68];

    const int tid = threadIdx.x;
    const int x0 = blockIdx.x * 64;
    const int Y0 = blockIdx.y * 16;
    const float TG22 = 0.4142135623730951f;

    // Phase 1: quantized img tile, replicate clamp at strip edges.
    for (int i = tid; i < 20 * 68; i += 256) {
        int yy = i / 68, xx = i - yy * 68;
        int GY = Y0 - 2 + yy; GY = max(0, min(HH - 1, GY));
        int GX = x0 - 2 + xx; GX = max(0, min(WD - 1, GX));
        int b = GY >> 9, y = GY & 511;
        const float* base = xin + (size_t)(((b * 3) << 9) + y) * 512 + GX;
        simg[0][yy][xx] = quant(base[0]);
        simg[1][yy][xx] = quant(base[1 << 18]);
        simg[2][yy][xx] = quant(base[2 << 18]);
    }
    __syncthreads();

    // Phase 2: mag+code for 18 rows x 66 cols (2 px per item, float2 loads).
    // mag[m][cc] center = img[m+1][cc+1]; global t = Y0-1+m, X = x0-1+cc.
    for (int item = tid; item < 594; item += 256) {
        int m  = item / 33;
        int tp = item - m * 33;
        int cc = 2 * tp;
        float bm0 = -1.0f, bgx0 = 0.0f, bgy0 = 0.0f;
        float bm1 = -1.0f, bgx1 = 0.0f, bgy1 = 0.0f;
#pragma unroll
        for (int ch = 0; ch < 3; ++ch) {
            const float* ip = &simg[ch][m][cc];
            float2 p00 = *(const float2*)(ip);
            float2 p01 = *(const float2*)(ip + 2);
            float2 p10 = *(const float2*)(ip + 68);
            float2 p11 = *(const float2*)(ip + 70);
            float2 p20 = *(const float2*)(ip + 136);
            float2 p21 = *(const float2*)(ip + 138);
            float aL0 = p00.x + 2.0f * p00.y + p01.x;
            float aR0 = p00.y + 2.0f * p01.x + p01.y;
            float dL0 = p01.x - p00.x, dR0 = p01.y - p00.y;
            float aL1 = p10.x + 2.0f * p10.y + p11.x;
            float aR1 = p10.y + 2.0f * p11.x + p11.y;
            float dL1 = p11.x - p10.x, dR1 = p11.y - p10.y;
            float aL2 = p20.x + 2.0f * p20.y + p21.x;
            float aR2 = p20.y + 2.0f * p21.x + p21.y;
            float dL2 = p21.x - p20.x, dR2 = p21.y - p20.y;
            float gxL = dL0 + 2.0f * dL1 + dL2, gyL = aL2 - aL0;
            float gxR = dR0 + 2.0f * dR1 + dR2, gyR = aR2 - aR0;
            float mgL = fabsf(gxL) + fabsf(gyL);
            float mgR = fabsf(gxR) + fabsf(gyR);
            if (mgL > bm0) { bm0 = mgL; bgx0 = gxL; bgy0 = gyL; }
            if (mgR > bm1) { bm1 = mgR; bgx1 = gxR; bgy1 = gyR; }
        }
        int t = Y0 - 1 + m;
        bool trow = (unsigned)t < (unsigned)HH;
        {
            int X = x0 - 1 + cc;
            unsigned wv = 0u;
            if (trow && (unsigned)X < (unsigned)WD) {
                float ax = fabsf(bgx0), ay = fabsf(bgy0);
                unsigned code = (ay < TG22 * ax) ? 0u
                              : ((ay * TG22 > ax) ? 1u
                              : ((bgx0 * bgy0 >= 0.0f) ? 2u : 3u));
                wv = (unsigned)(int)bm0 | (code << 16);
            }
            smag[m][cc] = wv;
        }
        {
            int X = x0 + cc;
            unsigned wv = 0u;
            if (trow && (unsigned)X < (unsigned)WD) {
                float ax = fabsf(bgx1), ay = fabsf(bgy1);
                unsigned code = (ay < TG22 * ax) ? 0u
                              : ((ay * TG22 > ax) ? 1u
                              : ((bgx1 * bgy1 >= 0.0f) ? 2u : 3u));
                wv = (unsigned)(int)bm1 | (code << 16);
            }
            smag[m][cc + 1] = wv;
        }
    }
    __syncthreads();

    // Phase 3: NMS compares + thresholds; ballot packs 32 cols per write.
    // n1 offsets: code 0 (h): (0,-1); 1 (v): (-1,0); 2: (-1,-1); 3: (-1,+1).
    const unsigned FULL = 0xffffffffu;
    const int lane = tid & 31;
    for (int i = tid; i < 1024; i += 256) {
        int py = i >> 6, pxc = i & 63;
        const unsigned* sp = &smag[0][0] + (py + 1) * 68 + (pxc + 1);
        unsigned w = sp[0];
        int mg = (int)(w & 0xFFFFu);
        unsigned code = w >> 16;
        int off = (code == 0u) ? -1
                : ((code == 1u) ? -68 : ((code == 2u) ? -69 : -67));
        int n1 = (int)(sp[off]  & 0xFFFFu);   // OOB words are 0 (zero-pad)
        int n2 = (int)(sp[-off] & 0xFFFFu);
        bool keep   = (mg > n1) && (mg >= n2);
        bool strong = keep && (mg > 200);
        bool weak   = keep && (mg > 100);
        unsigned bs = __ballot_sync(FULL, strong);
        unsigned bw = __ballot_sync(FULL, weak);
        if (lane == 0) {
            int u32idx = (Y0 + py) * 16 + (x0 >> 5) + (pxc >> 5);
            ((unsigned*)g_strong)[u32idx] = bs;
            ((unsigned*)g_weak)[u32idx]   = bw;
        }
    }
}

// ---------------------------------------------------------------------------
// Kernel 2: hysteresis — exactly (up to) 128 Jacobi dilation steps per launch
// (4 launches = the reference's 512-step cap, bit-exact). 128 blocks x 512
// threads (5 rows/thread), 64 interior rows + 128-row halo each side,
// double-buffered shared, early break on tile convergence.
// ---------------------------------------------------------------------------
__global__ __launch_bounds__(512) void k_hyst(int dir) {
    __shared__ unsigned long long bufA[TROWS * HPITCH];
    __shared__ unsigned long long bufB[TROWS * HPITCH];

    const unsigned long long* __restrict__ src = dir ? g_tmp : g_strong;
    unsigned long long* __restrict__ dst = dir ? g_strong : g_tmp;

    const int tid = threadIdx.x;
    const int base = blockIdx.x * INT_ROWS;

    for (int i = tid; i < TROWS * 8; i += 512) {
        int r = i >> 3, cc = i & 7;
        int gr = base - HALO + r;
        bufA[r * HPITCH + cc] = (gr >= 0 && gr < HH) ? src[gr * 8 + cc] : 0ull;
    }

    const int c = tid & 7;
    const int r0 = (tid >> 3) * 5;
    unsigned long long swr[5];
#pragma unroll
    for (int k = 0; k < 5; ++k) {
        int gr = base - HALO + r0 + k;
        swr[k] = (gr >= 0 && gr < HH) ? g_weak[gr * 8 + c] : 0ull;
    }
    __syncthreads();

    unsigned long long* cur = bufA;
    unsigned long long* nxt = bufB;

    for (int it = 0; it < 128; ++it) {
        auto hload = [&](int r, unsigned long long& h, unsigned long long& w) {
            if ((unsigned)r >= (unsigned)TROWS) { h = 0ull; w = 0ull; return; }
            unsigned long long ww = cur[r * HPITCH + c];
            unsigned long long wl = (c > 0) ? cur[r * HPITCH + c - 1] : 0ull;
            unsigned long long wr = (c < 7) ? cur[r * HPITCH + c + 1] : 0ull;
            w = ww;
            h = ww | (ww << 1) | (ww >> 1) | (wl >> 63) | (wr << 63);
        };
        unsigned long long Hm, H0, Hp, w0, wp, wd;
        hload(r0 - 1, Hm, wd);
        hload(r0, H0, w0);
        bool changed = false;
#pragma unroll
        for (int k = 0; k < 5; ++k) {
            hload(r0 + k + 1, Hp, wp);
            unsigned long long nw = ((Hm | H0 | Hp) & swr[k]) | w0;
            nxt[(r0 + k) * HPITCH + c] = nw;
            changed |= (nw != w0);
            Hm = H0; H0 = Hp; w0 = wp;
        }
        int any = __syncthreads_or(changed ? 1 : 0);
        unsigned long long* t = cur; cur = nxt; nxt = t;
        if (!any) break;
    }

    for (int i = tid; i < INT_ROWS * 8; i += 512) {
        int rr = i >> 3, cc = i & 7;
        dst[(base + rr) * 8 + cc] = cur[(HALO + rr) * HPITCH + cc];
    }
}

// ---------------------------------------------------------------------------
// Kernel 3: bitmask -> (B,3,H,W) float output, values {-1, +1}.
// 2 independent pixel-quads per thread (ILP), coalescing preserved.
// ---------------------------------------------------------------------------
__global__ __launch_bounds__(256) void k_out(float* __restrict__ out) {
    int idx = blockIdx.x * 256 + threadIdx.x;          // 0 .. 524287
#pragma unroll
    for (int half = 0; half < 2; ++half) {
        int q = idx + half * 524288;
        int p0 = q << 2;
        int Y = p0 >> 9;
        int X = p0 & 511;
        unsigned long long w = g_strong[Y * 8 + (X >> 6)];
        int sh = X & 63;
        float4 v;
        v.x = ((w >> sh) & 1ull) ? 1.0f : -1.0f;
        v.y = ((w >> (sh + 1)) & 1ull) ? 1.0f : -1.0f;
        v.z = ((w >> (sh + 2)) & 1ull) ? 1.0f : -1.0f;
        v.w = ((w >> (sh + 3)) & 1ull) ? 1.0f : -1.0f;
        int b = Y >> 9, y = Y & 511;
#pragma unroll
        for (int ch = 0; ch < 3; ++ch)
            *(float4*)&out[(((b * 3 + ch) << 9) + y) * 512 + X] = v;
    }
}

extern "C" void kernel_launch(void* const* d_in, const int* in_sizes, int n_in,
                              void* d_out, int out_size) {
    const float* x = (const float*)d_in[0];
    float* out = (float*)d_out;

    dim3 g1(WD / 64, HH / 16);                  // (8, 512)
    k_grad<<<g1, 256>>>(x);
    k_hyst<<<128, 512>>>(0);                    // steps   1..128  strong -> tmp
    k_hyst<<<128, 512>>>(1);                    // steps 129..256  tmp -> strong
    k_hyst<<<128, 512>>>(0);                    // steps 257..384  strong -> tmp
    k_hyst<<<128, 512>>>(1);                    // steps 385..512  tmp -> strong
    k_out<<<2048, 256>>>(out);
}

// round 15
// speedup vs baseline: 1.5705x; 1.0438x over previous
#include <cuda_runtime.h>
#include <cuda_bf16.h>

// Canny edge detection, exact replica of the JAX reference.
// Strip view: (B*H, W) = (8192, 512). Bitmask: 8 u64 (16 u32) words per row.

#define HH 8192
#define WD 512
#define TROWS 320          // hysteresis tile rows: 64 interior + 2*128 halo
#define HALO 128
#define INT_ROWS 64
#define HPITCH 9           // padded u64 pitch in shared

__device__ unsigned long long g_strong[HH * 8];
__device__ unsigned long long g_weak[HH * 8];
__device__ unsigned long long g_tmp[HH * 8];

__device__ __forceinline__ float quant(float v) {
    // input in [-1,1) -> result already in [0,255]; clip is redundant
    return floorf(((v + 1.0f) * 0.5f) * 255.0f);
}

// ---------------------------------------------------------------------------
// Kernel 1: quantize -> Sobel (replicate pad on strip) -> channel argmax ->
//   NMS direction code -> thresholds -> strong/weak bitmasks.
// 16x64 output tile, 256 threads, grid (8,512). smem 21 KB -> 8 blocks/SM.
//   P1: quantized 20x68x3 f32 img tile (interior blocks skip clamps).
//   P2: 18x66 mag region, 2 px/item via float2 loads; packs mag|code<<16,
//       zero-stores words outside the global image (NMS zero-pad).
//   P3: center + 2 code-directed neighbor reads, ballot packs bits.
// All arithmetic integer-exact in f32 -> bit-identical to the reference.
// ---------------------------------------------------------------------------
__global__ __launch_bounds__(256) void k_grad(const float* __restrict__ xin) {
    __shared__ __align__(16) float simg[3][20][68];
    __shared__ __align__(16) unsigned smag[18][68];

    const int tid = threadIdx.x;
    const int x0 = blockIdx.x * 64;
    const int Y0 = blockIdx.y * 16;
    const float TG22 = 0.4142135623730951f;
    const bool edge = (Y0 == 0) || (Y0 == HH - 16) || (x0 == 0) || (x0 == WD - 64);

    // Phase 1: quantized img tile, replicate clamp only for edge blocks.
    for (int i = tid; i < 20 * 68; i += 256) {
        int yy = i / 68, xx = i - yy * 68;
        int GY = Y0 - 2 + yy;
        int GX = x0 - 2 + xx;
        if (edge) {
            GY = max(0, min(HH - 1, GY));
            GX = max(0, min(WD - 1, GX));
        }
        int b = GY >> 9, y = GY & 511;
        const float* base = xin + (size_t)((b * 1536 + y) * 512 + GX);
        simg[0][yy][xx] = quant(base[0]);
        simg[1][yy][xx] = quant(base[1 << 18]);
        simg[2][yy][xx] = quant(base[2 << 18]);
    }
    __syncthreads();

    // Phase 2: mag+code for 18 rows x 66 cols (2 px per item, float2 loads).
    // mag[m][cc] center = img[m+1][cc+1]; global t = Y0-1+m, X = x0-1+cc.
    for (int item = tid; item < 594; item += 256) {
        int m  = item / 33;
        int tp = item - m * 33;
        int cc = 2 * tp;
        float bm0 = -1.0f, bgx0 = 0.0f, bgy0 = 0.0f;
        float bm1 = -1.0f, bgx1 = 0.0f, bgy1 = 0.0f;
#pragma unroll
        for (int ch = 0; ch < 3; ++ch) {
            const float* ip = &simg[ch][m][cc];
            float2 p00 = *(const float2*)(ip);
            float2 p01 = *(const float2*)(ip + 2);
            float2 p10 = *(const float2*)(ip + 68);
            float2 p11 = *(const float2*)(ip + 70);
            float2 p20 = *(const float2*)(ip + 136);
            float2 p21 = *(const float2*)(ip + 138);
            float aL0 = p00.x + 2.0f * p00.y + p01.x;
            float aR0 = p00.y + 2.0f * p01.x + p01.y;
            float dL0 = p01.x - p00.x, dR0 = p01.y - p00.y;
            float aL1 = p10.x + 2.0f * p10.y + p11.x;
            float aR1 = p10.y + 2.0f * p11.x + p11.y;
            float dL1 = p11.x - p10.x, dR1 = p11.y - p10.y;
            float aL2 = p20.x + 2.0f * p20.y + p21.x;
            float aR2 = p20.y + 2.0f * p21.x + p21.y;
            float dL2 = p21.x - p20.x, dR2 = p21.y - p20.y;
            float gxL = dL0 + 2.0f * dL1 + dL2, gyL = aL2 - aL0;
            float gxR = dR0 + 2.0f * dR1 + dR2, gyR = aR2 - aR0;
            float mgL = fabsf(gxL) + fabsf(gyL);
            float mgR = fabsf(gxR) + fabsf(gyR);
            if (mgL > bm0) { bm0 = mgL; bgx0 = gxL; bgy0 = gyL; }
            if (mgR > bm1) { bm1 = mgR; bgx1 = gxR; bgy1 = gyR; }
        }
        int t = Y0 - 1 + m;
        bool trow = (unsigned)t < (unsigned)HH;
        {
            int X = x0 - 1 + cc;
            unsigned wv = 0u;
            if (trow && (unsigned)X < (unsigned)WD) {
                float ax = fabsf(bgx0), ay = fabsf(bgy0);
                unsigned code = (ay < TG22 * ax) ? 0u
                              : ((ay * TG22 > ax) ? 1u
                              : ((bgx0 * bgy0 >= 0.0f) ? 2u : 3u));
                wv = (unsigned)(int)bm0 | (code << 16);
            }
            smag[m][cc] = wv;
        }
        {
            int X = x0 + cc;
            unsigned wv = 0u;
            if (trow && (unsigned)X < (unsigned)WD) {
                float ax = fabsf(bgx1), ay = fabsf(bgy1);
                unsigned code = (ay < TG22 * ax) ? 0u
                              : ((ay * TG22 > ax) ? 1u
                              : ((bgx1 * bgy1 >= 0.0f) ? 2u : 3u));
                wv = (unsigned)(int)bm1 | (code << 16);
            }
            smag[m][cc + 1] = wv;
        }
    }
    __syncthreads();

    // Phase 3: NMS compares + thresholds; ballot packs 32 cols per write.
    // n1 offsets: code 0 (h): (0,-1); 1 (v): (-1,0); 2: (-1,-1); 3: (-1,+1).
    const unsigned FULL = 0xffffffffu;
    const int lane = tid & 31;
    for (int i = tid; i < 1024; i += 256) {
        int py = i >> 6, pxc = i & 63;
        const unsigned* sp = &smag[0][0] + (py + 1) * 68 + (pxc + 1);
        unsigned w = sp[0];
        int mg = (int)(w & 0xFFFFu);
        unsigned code = w >> 16;
        int off = (code == 0u) ? -1
                : ((code == 1u) ? -68 : ((code == 2u) ? -69 : -67));
        int n1 = (int)(sp[off]  & 0xFFFFu);   // OOB words are 0 (zero-pad)
        int n2 = (int)(sp[-off] & 0xFFFFu);
        bool keep   = (mg > n1) && (mg >= n2);
        bool strong = keep && (mg > 200);
        bool weak   = keep && (mg > 100);
        unsigned bs = __ballot_sync(FULL, strong);
        unsigned bw = __ballot_sync(FULL, weak);
        if (lane == 0) {
            int u32idx = (Y0 + py) * 16 + (x0 >> 5) + (pxc >> 5);
            ((unsigned*)g_strong)[u32idx] = bs;
            ((unsigned*)g_weak)[u32idx]   = bw;
        }
    }
}

// ---------------------------------------------------------------------------
// Kernel 2: hysteresis — exactly (up to) 128 Jacobi dilation steps per launch
// (4 launches = the reference's 512-step cap, bit-exact). 128 blocks x 512
// threads (5 rows/thread), 64 interior rows + 128-row halo each side,
// double-buffered shared, early break on tile convergence.
// Final launch expands its interior rows straight to the float output.
// ---------------------------------------------------------------------------
__global__ __launch_bounds__(512) void k_hyst(int dir, float* __restrict__ out,
                                              int final_pass) {
    __shared__ unsigned long long bufA[TROWS * HPITCH];
    __shared__ unsigned long long bufB[TROWS * HPITCH];

    const unsigned long long* __restrict__ src = dir ? g_tmp : g_strong;
    unsigned long long* __restrict__ dst = dir ? g_strong : g_tmp;

    const int tid = threadIdx.x;
    const int base = blockIdx.x * INT_ROWS;

    for (int i = tid; i < TROWS * 8; i += 512) {
        int r = i >> 3, cc = i & 7;
        int gr = base - HALO + r;
        bufA[r * HPITCH + cc] = (gr >= 0 && gr < HH) ? src[gr * 8 + cc] : 0ull;
    }

    const int c = tid & 7;
    const int r0 = (tid >> 3) * 5;
    unsigned long long swr[5];
#pragma unroll
    for (int k = 0; k < 5; ++k) {
        int gr = base - HALO + r0 + k;
        swr[k] = (gr >= 0 && gr < HH) ? g_weak[gr * 8 + c] : 0ull;
    }
    __syncthreads();

    unsigned long long* cur = bufA;
    unsigned long long* nxt = bufB;

    for (int it = 0; it < 128; ++it) {
        auto hload = [&](int r, unsigned long long& h, unsigned long long& w) {
            if ((unsigned)r >= (unsigned)TROWS) { h = 0ull; w = 0ull; return; }
            unsigned long long ww = cur[r * HPITCH + c];
            unsigned long long wl = (c > 0) ? cur[r * HPITCH + c - 1] : 0ull;
            unsigned long long wr = (c < 7) ? cur[r * HPITCH + c + 1] : 0ull;
            w = ww;
            h = ww | (ww << 1) | (ww >> 1) | (wl >> 63) | (wr << 63);
        };
        unsigned long long Hm, H0, Hp, w0, wp, wd;
        hload(r0 - 1, Hm, wd);
        hload(r0, H0, w0);
        bool changed = false;
#pragma unroll
        for (int k = 0; k < 5; ++k) {
            hload(r0 + k + 1, Hp, wp);
            unsigned long long nw = ((Hm | H0 | Hp) & swr[k]) | w0;
            nxt[(r0 + k) * HPITCH + c] = nw;
            changed |= (nw != w0);
            Hm = H0; H0 = Hp; w0 = wp;
        }
        int any = __syncthreads_or(changed ? 1 : 0);
        unsigned long long* t = cur; cur = nxt; nxt = t;
        if (!any) break;
    }

    if (!final_pass) {
        for (int i = tid; i < INT_ROWS * 8; i += 512) {
            int rr = i >> 3, cc = i & 7;
            dst[(base + rr) * 8 + cc] = cur[(HALO + rr) * HPITCH + cc];
        }
    } else {
        // expand interior rows to (B,3,H,W) floats in {-1,+1}
        for (int i = tid; i < INT_ROWS * 128; i += 512) {
            int rr = i >> 7, qx = i & 127;
            int t = base + rr, X = qx << 2;
            unsigned long long w = cur[(HALO + rr) * HPITCH + (X >> 6)];
            int sh = X & 63;
            float4 v;
            v.x = ((w >> sh) & 1ull) ? 1.0f : -1.0f;
            v.y = ((w >> (sh + 1)) & 1ull) ? 1.0f : -1.0f;
            v.z = ((w >> (sh + 2)) & 1ull) ? 1.0f : -1.0f;
            v.w = ((w >> (sh + 3)) & 1ull) ? 1.0f : -1.0f;
            int b = t >> 9, y = t & 511;
#pragma unroll
            for (int ch = 0; ch < 3; ++ch)
                *(float4*)&out[(size_t)((b * 3 + ch) * 262144 + y * 512 + X)] = v;
        }
    }
}

extern "C" void kernel_launch(void* const* d_in, const int* in_sizes, int n_in,
                              void* d_out, int out_size) {
    const float* x = (const float*)d_in[0];
    float* out = (float*)d_out;

    dim3 g1(WD / 64, HH / 16);                  // (8, 512)
    k_grad<<<g1, 256>>>(x);
    k_hyst<<<128, 512>>>(0, nullptr, 0);        // steps   1..128  strong -> tmp
    k_hyst<<<128, 512>>>(1, nullptr, 0);        // steps 129..256  tmp -> strong
    k_hyst<<<128, 512>>>(0, nullptr, 0);        // steps 257..384  strong -> tmp
    k_hyst<<<128, 512>>>(1, out, 1);            // steps 385..512  tmp -> float out
}